// round 8
// baseline (speedup 1.0000x reference)
#include <cuda_runtime.h>
#include <cuda_fp16.h>

#define B 64
#define E 100000
#define C 80000
#define NNZ 1600000
#define NGROUPS 10000
#define GEPS 1e-5f
#define CAP 64
#define PBLK ((NNZ + 1023) / 1024)  // 1563 place-role blocks (4 nnz/thread)
#define TBLK (E / 32)               // 3125 transpose-role blocks

// __device__ scratch (allocation-free rule). Feature-major layouts [feat][B].
// Invariant: g_cnt_* are ZERO on entry to kernel_launch (zero-initialized .bss;
// gather kernels reset them to 0 after reading) -> no zeroing pass needed.
__device__ __align__(16) __half g_xTh[(size_t)E * B];        // 12.8 MB
__device__ __align__(16) __half g_hTh[(size_t)C * B];        // 10.2 MB
__device__ int g_cnt_c[C];
__device__ int g_cnt_e[E];
__device__ __align__(16) int2 g_ell_c[(size_t)C * CAP];      // 41 MB
__device__ __align__(16) int2 g_ell_e[(size_t)E * CAP];      // 51 MB

// ---------------------------------------------------------------------------
// prep: fused ELL-place (both layers, x4 unrolled for atomic MLP) + transpose
// x -> g_xTh (fp16). Place blocks first (longer pole, starts earliest).
// ---------------------------------------------------------------------------
__global__ void k_prep(const float* __restrict__ x,
                       const int* __restrict__ rows1, const int* __restrict__ cols1,
                       const float* __restrict__ vals1,
                       const int* __restrict__ rows2, const int* __restrict__ cols2,
                       const float* __restrict__ vals2) {
    __shared__ float tile[32][65];
    int tid = threadIdx.x;                 // 256 flat

    if (blockIdx.x < PBLK) {
        int i0 = blockIdx.x * 1024 + tid;
        int c1[4], r1[4], c2[4], r2[4];
        float v1[4], v2[4];
        bool ok[4];
        #pragma unroll
        for (int u = 0; u < 4; u++) {
            int i = i0 + u * 256;
            ok[u] = (i < NNZ);
            int is = ok[u] ? i : 0;
            c1[u] = cols1[is]; r1[u] = rows1[is]; v1[u] = vals1[is];
            c2[u] = cols2[is]; r2[u] = rows2[is]; v2[u] = vals2[is];
        }
        int p1[4], p2[4];
        #pragma unroll
        for (int u = 0; u < 4; u++) {      // 8 independent atomics in flight
            p1[u] = ok[u] ? atomicAdd(&g_cnt_c[c1[u]], 1) : CAP;
            p2[u] = ok[u] ? atomicAdd(&g_cnt_e[c2[u]], 1) : CAP;
        }
        #pragma unroll
        for (int u = 0; u < 4; u++) {
            if (p1[u] < CAP)
                g_ell_c[(size_t)c1[u] * CAP + p1[u]] =
                    make_int2(r1[u] * 128, __float_as_int(v1[u]));
            if (p2[u] < CAP)
                g_ell_e[(size_t)c2[u] * CAP + p2[u]] =
                    make_int2(r2[u] * 128, __float_as_int(v2[u]));
        }
        return;
    }

    // transpose role
    int bx = blockIdx.x - PBLK;
    int e0 = bx * 32;
    int tx = tid & 31, ty = tid >> 5;      // (32,8)

    #pragma unroll
    for (int b = ty; b < 64; b += 8)
        tile[tx][b] = x[(size_t)b * E + e0 + tx];   // coalesced over e
    __syncthreads();

    __half2* dst = reinterpret_cast<__half2*>(g_xTh);
    #pragma unroll
    for (int i = 0; i < 32; i += 8) {
        int e = e0 + ty + i;
        float lo = tile[ty + i][2 * tx + 0];
        float hi = tile[ty + i][2 * tx + 1];
        dst[(size_t)e * 32 + tx] = __floats2half2_rn(lo, hi);
    }
}

// ---------------------------------------------------------------------------
// Gather core (R6-proven v2): warp = one output feature. Lane q=lane&15 owns
// a batch quad (8B fp16); half=lane>>4 splits the nnz list. LDG.64 by 16 lanes
// covers one 128B row -> 2 nnz per load round; x2 unroll per half.
// fp32 accumulation; returns per-half float4, caller shfl-combines.
// ---------------------------------------------------------------------------
__device__ __forceinline__ float4 warp_gather_q(const int2* __restrict__ pr, int n,
                                                int2* spair, int lane,
                                                const char* __restrict__ src_base) {
    for (int j = lane; j < n; j += 32) spair[j] = __ldg(&pr[j]);
    __syncwarp();

    int q = lane & 15, half = lane >> 4;
    const char* src = src_base + q * 8;     // quad's 8B within each 128B row
    float4 a0 = {0.f, 0.f, 0.f, 0.f};
    float4 a1 = {0.f, 0.f, 0.f, 0.f};
    int j = half;
    for (; j + 2 < n; j += 4) {             // this half: j and j+2
        int2 p0 = spair[j];
        int2 p1 = spair[j + 2];
        float2 r0 = *reinterpret_cast<const float2*>(src + p0.x);
        float2 r1 = *reinterpret_cast<const float2*>(src + p1.x);
        float v0 = __int_as_float(p0.y);
        float v1 = __int_as_float(p1.y);
        float2 x00 = __half22float2(*reinterpret_cast<const __half2*>(&r0.x));
        float2 x01 = __half22float2(*reinterpret_cast<const __half2*>(&r0.y));
        float2 x10 = __half22float2(*reinterpret_cast<const __half2*>(&r1.x));
        float2 x11 = __half22float2(*reinterpret_cast<const __half2*>(&r1.y));
        a0.x += x00.x * v0; a0.y += x00.y * v0;
        a0.z += x01.x * v0; a0.w += x01.y * v0;
        a1.x += x10.x * v1; a1.y += x10.y * v1;
        a1.z += x11.x * v1; a1.w += x11.y * v1;
    }
    if (j < n) {
        int2 p = spair[j];
        float2 r = *reinterpret_cast<const float2*>(src + p.x);
        float v = __int_as_float(p.y);
        float2 xa = __half22float2(*reinterpret_cast<const __half2*>(&r.x));
        float2 xb = __half22float2(*reinterpret_cast<const __half2*>(&r.y));
        a0.x += xa.x * v; a0.y += xa.y * v;
        a0.z += xb.x * v; a0.w += xb.y * v;
    }
    float4 acc;
    acc.x = a0.x + a1.x; acc.y = a0.y + a1.y;
    acc.z = a0.z + a1.z; acc.w = a0.w + a1.w;
    return acc;
}

__device__ __forceinline__ float4 combine_halves(float4 acc) {
    acc.x += __shfl_xor_sync(0xffffffffu, acc.x, 16);
    acc.y += __shfl_xor_sync(0xffffffffu, acc.y, 16);
    acc.z += __shfl_xor_sync(0xffffffffu, acc.z, 16);
    acc.w += __shfl_xor_sync(0xffffffffu, acc.w, 16);
    return acc;
}

// ---------------------------------------------------------------------------
// gather_in fused with GroupLayerNorm + ELU. Block = 1 group = 8 channels.
// Reads + RESETS g_cnt_c (maintains zero-on-entry invariant).
// ---------------------------------------------------------------------------
__global__ void k_gather_in_norm(const float* __restrict__ b_in,
                                 const float* __restrict__ gamma,
                                 const float* __restrict__ beta) {
    __shared__ __align__(16) int2 spair[8][CAP];    // 4 KB
    __shared__ float sh[8][64];
    __shared__ float s_mean[64], s_inv[64];
    int g = blockIdx.x;
    int w = threadIdx.x >> 5;
    int lane = threadIdx.x & 31;
    int q = lane & 15, half = lane >> 4;
    int c = g * 8 + w;

    int n_raw = 0;
    if (lane == 0) {
        n_raw = g_cnt_c[c];
        g_cnt_c[c] = 0;                    // reset for next launch
    }
    n_raw = __shfl_sync(0xffffffffu, n_raw, 0);
    int n = min(n_raw, CAP);

    float4 acc = warp_gather_q(&g_ell_c[(size_t)c * CAP], n, spair[w], lane,
                               reinterpret_cast<const char*>(g_xTh));
    acc = combine_halves(acc);
    if (half == 0) {
        float bi = b_in[c];
        sh[w][4 * q + 0] = acc.x + bi;
        sh[w][4 * q + 1] = acc.y + bi;
        sh[w][4 * q + 2] = acc.z + bi;
        sh[w][4 * q + 3] = acc.w + bi;
    }
    __syncthreads();

    if (threadIdx.x < 64) {
        int b = threadIdx.x;
        float s = 0.f, ss = 0.f;
        #pragma unroll
        for (int r = 0; r < 8; r++) {
            float h = sh[r][b];
            s += h; ss += h * h;
        }
        float mean = s * 0.125f;
        float var = ss * 0.125f - mean * mean;
        s_mean[b] = mean;
        s_inv[b] = rsqrtf(var + GEPS);
    }
    __syncthreads();

    // normalize + affine + ELU -> half2. Thread t: r = t>>5, batch pair bp = t&31.
    {
        int r = threadIdx.x >> 5;
        int bp = threadIdx.x & 31;
        int b0 = 2 * bp, b1 = 2 * bp + 1;
        float ga = gamma[g * 8 + r], be = beta[g * 8 + r];
        float y0 = ga * ((sh[r][b0] - s_mean[b0]) * s_inv[b0]) + be;
        float y1 = ga * ((sh[r][b1] - s_mean[b1]) * s_inv[b1]) + be;
        y0 = (y0 > 0.f) ? y0 : (__expf(y0) - 1.f);
        y1 = (y1 > 0.f) ? y1 : (__expf(y1) - 1.f);
        reinterpret_cast<__half2*>(g_hTh)[(size_t)(g * 8 + r) * 32 + bp] =
            __floats2half2_rn(y0, y1);
    }
}

// ---------------------------------------------------------------------------
// gather_out + bias + residual(fp32 x) + fused transpose to out[b][e].
// Block = 8 consecutive edges. Reads + RESETS g_cnt_e.
// ---------------------------------------------------------------------------
__global__ void k_gather_out(const float* __restrict__ x,
                             const float* __restrict__ b_out,
                             float* __restrict__ out) {
    __shared__ __align__(16) int2 spair[8][CAP];
    __shared__ float sh[8][68];             // padded
    int e0 = blockIdx.x * 8;
    int w = threadIdx.x >> 5;
    int lane = threadIdx.x & 31;
    int q = lane & 15, half = lane >> 4;
    int e = e0 + w;

    int n_raw = 0;
    if (lane == 0) {
        n_raw = g_cnt_e[e];
        g_cnt_e[e] = 0;                    // reset for next launch
    }
    n_raw = __shfl_sync(0xffffffffu, n_raw, 0);
    int n = min(n_raw, CAP);

    float4 acc = warp_gather_q(&g_ell_e[(size_t)e * CAP], n, spair[w], lane,
                               reinterpret_cast<const char*>(g_hTh));
    acc = combine_halves(acc);
    if (half == 0) {
        float bo = b_out[e];
        sh[w][4 * q + 0] = acc.x + bo;
        sh[w][4 * q + 1] = acc.y + bo;
        sh[w][4 * q + 2] = acc.z + bo;
        sh[w][4 * q + 3] = acc.w + bo;
    }
    __syncthreads();

    // write phase: thread t -> b = t>>2, e_local = (t&3)*2; float2 per thread.
    int b = threadIdx.x >> 2;
    int el = (threadIdx.x & 3) * 2;
    size_t gidx = (size_t)b * E + e0 + el;
    float2 xv = *reinterpret_cast<const float2*>(&x[gidx]);
    float2 o;
    o.x = sh[el + 0][b] + xv.x;
    o.y = sh[el + 1][b] + xv.y;
    *reinterpret_cast<float2*>(&out[gidx]) = o;
}

// ---------------------------------------------------------------------------
// inputs: 0:x 1:v_in 2:b_in 3:v_out 4:b_out 5:gamma 6:beta
// 7:w_in_rows 8:w_in_cols 9:w_out_rows 10:w_out_cols 11:channel_groups(unused)
// ---------------------------------------------------------------------------
extern "C" void kernel_launch(void* const* d_in, const int* in_sizes, int n_in,
                              void* d_out, int out_size) {
    const float* x      = (const float*)d_in[0];
    const float* v_in   = (const float*)d_in[1];
    const float* b_in   = (const float*)d_in[2];
    const float* v_out  = (const float*)d_in[3];
    const float* b_out  = (const float*)d_in[4];
    const float* gamma  = (const float*)d_in[5];
    const float* beta   = (const float*)d_in[6];
    const int* w_in_rows  = (const int*)d_in[7];
    const int* w_in_cols  = (const int*)d_in[8];
    const int* w_out_rows = (const int*)d_in[9];
    const int* w_out_cols = (const int*)d_in[10];
    float* out = (float*)d_out;

    k_prep<<<PBLK + TBLK, 256>>>(x, w_in_rows, w_in_cols, v_in,
                                 w_out_rows, w_out_cols, v_out);
    k_gather_in_norm<<<NGROUPS, 256>>>(b_in, gamma, beta);
    k_gather_out<<<E / 8, 256>>>(x, b_out, out);
}

// round 11
// speedup vs baseline: 3.7200x; 3.7200x over previous
#include <cuda_runtime.h>
#include <cuda_fp16.h>

#define B 64
#define E 100000
#define C 80000
#define NNZ 1600000
#define NGROUPS 10000
#define GEPS 1e-5f
#define CAP 64

// __device__ scratch (allocation-free rule). Feature-major layouts [feat][B].
__device__ __align__(16) __half g_xTh[(size_t)E * B];        // 12.8 MB
__device__ __align__(16) __half g_hTh[(size_t)C * B];        // 10.2 MB
__device__ int g_cnt_c[C];
__device__ int g_cnt_e[E];
__device__ __align__(16) int2 g_ell_c[(size_t)C * CAP];      // 41 MB
__device__ __align__(16) int2 g_ell_e[(size_t)E * CAP];      // 51 MB

// ---------------------------------------------------------------------------
// transpose x [B,E] -> g_xTh [E,B] (fp16); also zeroes both ELL counters.
// ---------------------------------------------------------------------------
__global__ void k_transpose_in(const float* __restrict__ x) {
    __shared__ float tile[32][65];          // [e_local][b]
    int e0 = blockIdx.x * 32;
    int tx = threadIdx.x, ty = threadIdx.y; // (32,8)
    int tid = ty * 32 + tx;

    int zi = blockIdx.x * 256 + tid;
    if (zi < C) g_cnt_c[zi] = 0;
    if (zi < E) g_cnt_e[zi] = 0;

    #pragma unroll
    for (int b = ty; b < 64; b += 8)
        tile[tx][b] = x[(size_t)b * E + e0 + tx];   // coalesced over e
    __syncthreads();

    __half2* dst = reinterpret_cast<__half2*>(g_xTh);
    #pragma unroll
    for (int i = 0; i < 32; i += 8) {
        int e = e0 + ty + i;
        float lo = tile[ty + i][2 * tx + 0];
        float hi = tile[ty + i][2 * tx + 1];
        dst[(size_t)e * 32 + tx] = __floats2half2_rn(lo, hi);
    }
}

// ---------------------------------------------------------------------------
// ELL build, both layers in one pass. Stores (row*128 byte-offset, bits(val)).
// Loads hoisted and both atomics issued before either store (2 chains in flight).
// ---------------------------------------------------------------------------
__global__ void k_place_both(const int* __restrict__ rows1,
                             const int* __restrict__ cols1,
                             const float* __restrict__ vals1,
                             const int* __restrict__ rows2,
                             const int* __restrict__ cols2,
                             const float* __restrict__ vals2) {
    int i = blockIdx.x * blockDim.x + threadIdx.x;
    if (i >= NNZ) return;
    int c1 = cols1[i], r1 = rows1[i];
    int c2 = cols2[i], r2 = rows2[i];
    float v1 = vals1[i], v2 = vals2[i];
    int p1 = atomicAdd(&g_cnt_c[c1], 1);
    int p2 = atomicAdd(&g_cnt_e[c2], 1);
    if (p1 < CAP)
        g_ell_c[(size_t)c1 * CAP + p1] = make_int2(r1 * 128, __float_as_int(v1));
    if (p2 < CAP)
        g_ell_e[(size_t)c2 * CAP + p2] = make_int2(r2 * 128, __float_as_int(v2));
}

// ---------------------------------------------------------------------------
// Gather core (R6-proven v2): warp = one output feature. Lane q=lane&15 owns
// a batch quad (8B fp16); half=lane>>4 splits the nnz list. LDG.64 by 16 lanes
// covers one 128B row -> warp retires 2 nnz per load round; x2 unroll per half.
// fp32 accumulation; returns per-half float4, caller shfl-combines.
// ---------------------------------------------------------------------------
__device__ __forceinline__ float4 warp_gather_q(const int2* __restrict__ pr, int n,
                                                int2* spair, int lane,
                                                const char* __restrict__ src_base) {
    for (int j = lane; j < n; j += 32) spair[j] = __ldg(&pr[j]);
    __syncwarp();

    int q = lane & 15, half = lane >> 4;
    const char* src = src_base + q * 8;     // quad's 8B within each 128B row
    float4 a0 = {0.f, 0.f, 0.f, 0.f};
    float4 a1 = {0.f, 0.f, 0.f, 0.f};
    int j = half;
    for (; j + 2 < n; j += 4) {             // this half: j and j+2
        int2 p0 = spair[j];
        int2 p1 = spair[j + 2];
        float2 r0 = *reinterpret_cast<const float2*>(src + p0.x);
        float2 r1 = *reinterpret_cast<const float2*>(src + p1.x);
        float v0 = __int_as_float(p0.y);
        float v1 = __int_as_float(p1.y);
        float2 x00 = __half22float2(*reinterpret_cast<const __half2*>(&r0.x));
        float2 x01 = __half22float2(*reinterpret_cast<const __half2*>(&r0.y));
        float2 x10 = __half22float2(*reinterpret_cast<const __half2*>(&r1.x));
        float2 x11 = __half22float2(*reinterpret_cast<const __half2*>(&r1.y));
        a0.x += x00.x * v0; a0.y += x00.y * v0;
        a0.z += x01.x * v0; a0.w += x01.y * v0;
        a1.x += x10.x * v1; a1.y += x10.y * v1;
        a1.z += x11.x * v1; a1.w += x11.y * v1;
    }
    if (j < n) {
        int2 p = spair[j];
        float2 r = *reinterpret_cast<const float2*>(src + p.x);
        float v = __int_as_float(p.y);
        float2 xa = __half22float2(*reinterpret_cast<const __half2*>(&r.x));
        float2 xb = __half22float2(*reinterpret_cast<const __half2*>(&r.y));
        a0.x += xa.x * v; a0.y += xa.y * v;
        a0.z += xb.x * v; a0.w += xb.y * v;
    }
    float4 acc;
    acc.x = a0.x + a1.x; acc.y = a0.y + a1.y;
    acc.z = a0.z + a1.z; acc.w = a0.w + a1.w;
    return acc;
}

__device__ __forceinline__ float4 combine_halves(float4 acc) {
    acc.x += __shfl_xor_sync(0xffffffffu, acc.x, 16);
    acc.y += __shfl_xor_sync(0xffffffffu, acc.y, 16);
    acc.z += __shfl_xor_sync(0xffffffffu, acc.z, 16);
    acc.w += __shfl_xor_sync(0xffffffffu, acc.w, 16);
    return acc;
}

// ---------------------------------------------------------------------------
// gather_in fused with GroupLayerNorm + ELU. Block = 1 group = 8 channels.
// ---------------------------------------------------------------------------
__global__ void k_gather_in_norm(const float* __restrict__ b_in,
                                 const float* __restrict__ gamma,
                                 const float* __restrict__ beta) {
    __shared__ __align__(16) int2 spair[8][CAP];    // 4 KB
    __shared__ float sh[8][64];
    __shared__ float s_mean[64], s_inv[64];
    int g = blockIdx.x;
    int w = threadIdx.x >> 5;
    int lane = threadIdx.x & 31;
    int q = lane & 15, half = lane >> 4;
    int c = g * 8 + w;

    int n = min(g_cnt_c[c], CAP);
    float4 acc = warp_gather_q(&g_ell_c[(size_t)c * CAP], n, spair[w], lane,
                               reinterpret_cast<const char*>(g_xTh));
    acc = combine_halves(acc);
    if (half == 0) {
        float bi = b_in[c];
        sh[w][4 * q + 0] = acc.x + bi;
        sh[w][4 * q + 1] = acc.y + bi;
        sh[w][4 * q + 2] = acc.z + bi;
        sh[w][4 * q + 3] = acc.w + bi;
    }
    __syncthreads();

    if (threadIdx.x < 64) {
        int b = threadIdx.x;
        float s = 0.f, ss = 0.f;
        #pragma unroll
        for (int r = 0; r < 8; r++) {
            float h = sh[r][b];
            s += h; ss += h * h;
        }
        float mean = s * 0.125f;
        float var = ss * 0.125f - mean * mean;
        s_mean[b] = mean;
        s_inv[b] = rsqrtf(var + GEPS);
    }
    __syncthreads();

    // normalize + affine + ELU -> half2. Thread t: r = t>>5, batch pair bp = t&31.
    {
        int r = threadIdx.x >> 5;
        int bp = threadIdx.x & 31;
        int b0 = 2 * bp, b1 = 2 * bp + 1;
        float ga = gamma[g * 8 + r], be = beta[g * 8 + r];
        float y0 = ga * ((sh[r][b0] - s_mean[b0]) * s_inv[b0]) + be;
        float y1 = ga * ((sh[r][b1] - s_mean[b1]) * s_inv[b1]) + be;
        y0 = (y0 > 0.f) ? y0 : (__expf(y0) - 1.f);
        y1 = (y1 > 0.f) ? y1 : (__expf(y1) - 1.f);
        reinterpret_cast<__half2*>(g_hTh)[(size_t)(g * 8 + r) * 32 + bp] =
            __floats2half2_rn(y0, y1);
    }
}

// ---------------------------------------------------------------------------
// gather_out + bias + residual(fp32 x) + fused transpose to out[b][e].
// Block = 8 consecutive edges.
// ---------------------------------------------------------------------------
__global__ void k_gather_out(const float* __restrict__ x,
                             const float* __restrict__ b_out,
                             float* __restrict__ out) {
    __shared__ __align__(16) int2 spair[8][CAP];
    __shared__ float sh[8][68];             // padded
    int e0 = blockIdx.x * 8;
    int w = threadIdx.x >> 5;
    int lane = threadIdx.x & 31;
    int q = lane & 15, half = lane >> 4;
    int e = e0 + w;

    int n = min(g_cnt_e[e], CAP);
    float4 acc = warp_gather_q(&g_ell_e[(size_t)e * CAP], n, spair[w], lane,
                               reinterpret_cast<const char*>(g_hTh));
    acc = combine_halves(acc);
    if (half == 0) {
        float bo = b_out[e];
        sh[w][4 * q + 0] = acc.x + bo;
        sh[w][4 * q + 1] = acc.y + bo;
        sh[w][4 * q + 2] = acc.z + bo;
        sh[w][4 * q + 3] = acc.w + bo;
    }
    __syncthreads();

    // write phase: thread t -> b = t>>2, e_local = (t&3)*2; float2 per thread.
    int b = threadIdx.x >> 2;
    int el = (threadIdx.x & 3) * 2;
    size_t gidx = (size_t)b * E + e0 + el;
    float2 xv = *reinterpret_cast<const float2*>(&x[gidx]);
    float2 o;
    o.x = sh[el + 0][b] + xv.x;
    o.y = sh[el + 1][b] + xv.y;
    *reinterpret_cast<float2*>(&out[gidx]) = o;
}

// ---------------------------------------------------------------------------
// inputs: 0:x 1:v_in 2:b_in 3:v_out 4:b_out 5:gamma 6:beta
// 7:w_in_rows 8:w_in_cols 9:w_out_rows 10:w_out_cols 11:channel_groups(unused)
// ---------------------------------------------------------------------------
extern "C" void kernel_launch(void* const* d_in, const int* in_sizes, int n_in,
                              void* d_out, int out_size) {
    const float* x      = (const float*)d_in[0];
    const float* v_in   = (const float*)d_in[1];
    const float* b_in   = (const float*)d_in[2];
    const float* v_out  = (const float*)d_in[3];
    const float* b_out  = (const float*)d_in[4];
    const float* gamma  = (const float*)d_in[5];
    const float* beta   = (const float*)d_in[6];
    const int* w_in_rows  = (const int*)d_in[7];
    const int* w_in_cols  = (const int*)d_in[8];
    const int* w_out_rows = (const int*)d_in[9];
    const int* w_out_cols = (const int*)d_in[10];
    float* out = (float*)d_out;

    dim3 tb(32, 8);

    k_transpose_in<<<E / 32, tb>>>(x);      // also zeroes counters
    k_place_both<<<(NNZ + 255) / 256, 256>>>(w_in_rows, w_in_cols, v_in,
                                             w_out_rows, w_out_cols, v_out);
    k_gather_in_norm<<<NGROUPS, 256>>>(b_in, gamma, beta);
    k_gather_out<<<E / 8, 256>>>(x, b_out, out);
}